// round 1
// baseline (speedup 1.0000x reference)
#include <cuda_runtime.h>
#include <math.h>

// Problem constants
#define B_    64
#define S_    200
#define H_    16
#define DK_   64
#define DM_   1024
#define MROWS (B_ * S_)          // 12800
#define BH_   (B_ * H_)          // 1024
#define OUT_N  ((size_t)MROWS * DM_)       // 13107200
#define ATTN_N ((size_t)BH_ * S_ * S_)     // 40960000

// Scratch (allocation-free rule: __device__ globals)
__device__ float g_Q[BH_ * S_ * DK_];
__device__ float g_K[BH_ * S_ * DK_];
__device__ float g_V[BH_ * S_ * DK_];
__device__ float g_ctx[MROWS * DM_];
__device__ float g_attn_fb[BH_ * S_ * S_];   // fallback if d_out only holds 'out'
__device__ float g_out_fb[MROWS * DM_];      // fallback if d_out only holds 'attn'

// ---------------------------------------------------------------------------
// Projection GEMM: C = A[M,1024] @ W^T[1024,1024] + bias
// OUT_MODE 0: scatter into [b,h,s,dk] layout (QKV). OUT_MODE 1: plain [m,n].
// 128x128 block tile, BK=16, 256 threads, 8x8 register tile.
// ---------------------------------------------------------------------------
template <int OUT_MODE>
__global__ void __launch_bounds__(256) proj_gemm(
    const float* __restrict__ A, const float* __restrict__ W,
    const float* __restrict__ bias, float* __restrict__ C)
{
    __shared__ float As[16][132];   // [k][m], pad keeps float4 alignment
    __shared__ float Bs[16][132];   // [k][n]

    const int tid = threadIdx.x;
    const int m0  = blockIdx.y * 128;
    const int n0  = blockIdx.x * 128;
    const int tx  = tid & 15;       // 0..15 -> n
    const int ty  = tid >> 4;       // 0..15 -> m
    const int lrow = tid >> 2;      // 0..63
    const int lcol = (tid & 3) << 2; // 0,4,8,12

    float acc[8][8];
#pragma unroll
    for (int i = 0; i < 8; i++)
#pragma unroll
        for (int j = 0; j < 8; j++) acc[i][j] = 0.f;

    const float* Aptr = A + (size_t)m0 * DM_ + lcol;
    const float* Wptr = W + (size_t)n0 * DM_ + lcol;

    for (int k0 = 0; k0 < DM_; k0 += 16) {
#pragma unroll
        for (int i = 0; i < 2; i++) {
            int r = lrow + i * 64;
            float4 va = *(const float4*)(Aptr + (size_t)r * DM_ + k0);
            float4 vb = *(const float4*)(Wptr + (size_t)r * DM_ + k0);
            As[lcol + 0][r] = va.x; As[lcol + 1][r] = va.y;
            As[lcol + 2][r] = va.z; As[lcol + 3][r] = va.w;
            Bs[lcol + 0][r] = vb.x; Bs[lcol + 1][r] = vb.y;
            Bs[lcol + 2][r] = vb.z; Bs[lcol + 3][r] = vb.w;
        }
        __syncthreads();
#pragma unroll
        for (int k = 0; k < 16; k++) {
            float ra[8], rb[8];
            *(float4*)&ra[0] = *(const float4*)&As[k][ty * 8];
            *(float4*)&ra[4] = *(const float4*)&As[k][ty * 8 + 4];
            *(float4*)&rb[0] = *(const float4*)&Bs[k][tx * 8];
            *(float4*)&rb[4] = *(const float4*)&Bs[k][tx * 8 + 4];
#pragma unroll
            for (int i = 0; i < 8; i++)
#pragma unroll
                for (int j = 0; j < 8; j++)
                    acc[i][j] = fmaf(ra[i], rb[j], acc[i][j]);
        }
        __syncthreads();
    }

    const int n_base = n0 + tx * 8;
    float bn[8];
#pragma unroll
    for (int j = 0; j < 8; j++) bn[j] = bias[n_base + j];

#pragma unroll
    for (int i = 0; i < 8; i++) {
        int m = m0 + ty * 8 + i;              // < 12800 always (12800 = 100*128)
        if (OUT_MODE == 0) {
            int bb = m / S_;
            int ss = m - bb * S_;
            int hh = n_base >> 6;             // constant over j (8 <= 64 block)
            int dk = n_base & 63;
            float* dst = C + ((((size_t)bb * H_ + hh) * S_) + ss) * DK_ + dk;
            float4 w0, w1;
            w0.x = acc[i][0] + bn[0]; w0.y = acc[i][1] + bn[1];
            w0.z = acc[i][2] + bn[2]; w0.w = acc[i][3] + bn[3];
            w1.x = acc[i][4] + bn[4]; w1.y = acc[i][5] + bn[5];
            w1.z = acc[i][6] + bn[6]; w1.w = acc[i][7] + bn[7];
            *(float4*)(dst)     = w0;
            *(float4*)(dst + 4) = w1;
        } else {
            float* dst = C + (size_t)m * DM_ + n_base;
            float4 w0, w1;
            w0.x = acc[i][0] + bn[0]; w0.y = acc[i][1] + bn[1];
            w0.z = acc[i][2] + bn[2]; w0.w = acc[i][3] + bn[3];
            w1.x = acc[i][4] + bn[4]; w1.y = acc[i][5] + bn[5];
            w1.z = acc[i][6] + bn[6]; w1.w = acc[i][7] + bn[7];
            *(float4*)(dst)     = w0;
            *(float4*)(dst + 4) = w1;
        }
    }
}

// ---------------------------------------------------------------------------
// Scores: attn[bh,i,j] = Q[bh,i,:]·K[bh,j,:] / 8 + bias[h,i,j], masked.
// Block: one (bh, 64x64 tile). 256 threads, 4x4 register tile.
// ---------------------------------------------------------------------------
__global__ void __launch_bounds__(256) scores_kernel(
    const float* __restrict__ tb, const int* __restrict__ mask,
    float* __restrict__ attn)
{
    const int bh = blockIdx.z;
    const int b  = bh >> 4;
    const int h  = bh & 15;
    const int i0 = blockIdx.y * 64;
    const int j0 = blockIdx.x * 64;

    const float* Q = g_Q + (size_t)bh * S_ * DK_;
    const float* K = g_K + (size_t)bh * S_ * DK_;

    __shared__ float Qs[64][65];  // transposed: [k][i]
    __shared__ float Ks[64][65];  // transposed: [k][j]

    const int tid = threadIdx.x;
    const int r   = tid >> 4;        // 0..15
    const int c4  = (tid & 15) << 2; // 0..60

#pragma unroll
    for (int it = 0; it < 4; it++) {
        int row = r + it * 16;
        int gi = i0 + row, gj = j0 + row;
        float4 vq = make_float4(0.f, 0.f, 0.f, 0.f);
        float4 vk = make_float4(0.f, 0.f, 0.f, 0.f);
        if (gi < S_) vq = *(const float4*)&Q[(size_t)gi * DK_ + c4];
        if (gj < S_) vk = *(const float4*)&K[(size_t)gj * DK_ + c4];
        Qs[c4 + 0][row] = vq.x; Qs[c4 + 1][row] = vq.y;
        Qs[c4 + 2][row] = vq.z; Qs[c4 + 3][row] = vq.w;
        Ks[c4 + 0][row] = vk.x; Ks[c4 + 1][row] = vk.y;
        Ks[c4 + 2][row] = vk.z; Ks[c4 + 3][row] = vk.w;
    }
    __syncthreads();

    const int tx = tid & 15, ty = tid >> 4;
    float acc[4][4];
#pragma unroll
    for (int i = 0; i < 4; i++)
#pragma unroll
        for (int j = 0; j < 4; j++) acc[i][j] = 0.f;

#pragma unroll 8
    for (int k = 0; k < 64; k++) {
        float ra[4], rb[4];
#pragma unroll
        for (int ii = 0; ii < 4; ii++) ra[ii] = Qs[k][ty * 4 + ii];
#pragma unroll
        for (int jj = 0; jj < 4; jj++) rb[jj] = Ks[k][tx * 4 + jj];
#pragma unroll
        for (int ii = 0; ii < 4; ii++)
#pragma unroll
            for (int jj = 0; jj < 4; jj++)
                acc[ii][jj] = fmaf(ra[ii], rb[jj], acc[ii][jj]);
    }

    const float* tbh  = tb + (size_t)h * S_ * S_;
    const int*   mb   = mask + (size_t)b * S_ * S_;
    float*       outp = attn + (size_t)bh * S_ * S_;

#pragma unroll
    for (int ii = 0; ii < 4; ii++) {
        int gi = i0 + ty * 4 + ii;
        if (gi >= S_) continue;
#pragma unroll
        for (int jj = 0; jj < 4; jj++) {
            int gj = j0 + tx * 4 + jj;
            if (gj >= S_) continue;
            float v = acc[ii][jj] * 0.125f + tbh[gi * S_ + gj];
            if (mb[gi * S_ + gj] == 0) v = -1e9f;
            outp[gi * S_ + gj] = v;
        }
    }
}

// ---------------------------------------------------------------------------
// Row softmax in place (warp per row of length 200)
// ---------------------------------------------------------------------------
__global__ void __launch_bounds__(256) softmax_kernel(float* __restrict__ attn)
{
    const int gwarp = (blockIdx.x * blockDim.x + threadIdx.x) >> 5;
    const int lane  = threadIdx.x & 31;
    if (gwarp >= BH_ * S_) return;
    float* row = attn + (size_t)gwarp * S_;

    float v[7];
    float mx = -1e30f;
#pragma unroll
    for (int t = 0; t < 7; t++) {
        int j = lane + t * 32;
        v[t] = (j < S_) ? row[j] : -1e30f;
        mx = fmaxf(mx, v[t]);
    }
#pragma unroll
    for (int o = 16; o > 0; o >>= 1) mx = fmaxf(mx, __shfl_xor_sync(0xffffffffu, mx, o));

    float sum = 0.f;
#pragma unroll
    for (int t = 0; t < 7; t++) {
        int j = lane + t * 32;
        v[t] = (j < S_) ? expf(v[t] - mx) : 0.f;
        sum += v[t];
    }
#pragma unroll
    for (int o = 16; o > 0; o >>= 1) sum += __shfl_xor_sync(0xffffffffu, sum, o);

    const float inv = 1.f / sum;
#pragma unroll
    for (int t = 0; t < 7; t++) {
        int j = lane + t * 32;
        if (j < S_) row[j] = v[t] * inv;
    }
}

// ---------------------------------------------------------------------------
// ctx[b,s,h*64+dk] = sum_j attn[bh,s,j] * V[bh,j,dk]
// Block: (bh, 64-row i tile). BK=8 over K=200. 256 threads, 4x4 tile.
// ---------------------------------------------------------------------------
__global__ void __launch_bounds__(256) ctx_kernel(const float* __restrict__ attn)
{
    const int bh = blockIdx.y;
    const int b  = bh >> 4;
    const int h  = bh & 15;
    const int i0 = blockIdx.x * 64;

    const float* Arow = attn + (size_t)bh * S_ * S_;
    const float* V    = g_V  + (size_t)bh * S_ * DK_;

    __shared__ float As[8][65];   // [k][i]
    __shared__ float Vs[8][64];   // [k][d]

    const int tid = threadIdx.x;
    const int tx = tid & 15, ty = tid >> 4;

    float acc[4][4];
#pragma unroll
    for (int i = 0; i < 4; i++)
#pragma unroll
        for (int j = 0; j < 4; j++) acc[i][j] = 0.f;

    const int ai = tid >> 2;          // 0..63
    const int ak = (tid & 3) << 1;    // 0,2,4,6
    const int vk = tid >> 5;          // 0..7
    const int vd = (tid & 31) << 1;   // 0..62

    for (int k0 = 0; k0 < S_; k0 += 8) {
        int gi = i0 + ai;
        float2 va = make_float2(0.f, 0.f);
        if (gi < S_) va = *(const float2*)&Arow[(size_t)gi * S_ + k0 + ak];
        As[ak][ai] = va.x; As[ak + 1][ai] = va.y;

        float2 vv = *(const float2*)&V[(size_t)(k0 + vk) * DK_ + vd];
        *(float2*)&Vs[vk][vd] = vv;
        __syncthreads();

#pragma unroll
        for (int k = 0; k < 8; k++) {
            float ra[4], rb[4];
#pragma unroll
            for (int ii = 0; ii < 4; ii++) ra[ii] = As[k][ty * 4 + ii];
            *(float4*)&rb[0] = *(const float4*)&Vs[k][tx * 4];
#pragma unroll
            for (int ii = 0; ii < 4; ii++)
#pragma unroll
                for (int jj = 0; jj < 4; jj++)
                    acc[ii][jj] = fmaf(ra[ii], rb[jj], acc[ii][jj]);
        }
        __syncthreads();
    }

#pragma unroll
    for (int ii = 0; ii < 4; ii++) {
        int ss = i0 + ty * 4 + ii;
        if (ss >= S_) continue;
        float* dst = g_ctx + ((size_t)b * S_ + ss) * DM_ + h * DK_ + tx * 4;
        *(float4*)dst = *(float4*)&acc[ii][0];
    }
}

// ---------------------------------------------------------------------------
extern "C" void kernel_launch(void* const* d_in, const int* in_sizes, int n_in,
                              void* d_out, int out_size)
{
    const float* x    = (const float*)d_in[0];
    const int*   mask = (const int*)  d_in[1];
    const float* wq   = (const float*)d_in[2];
    const float* bq   = (const float*)d_in[3];
    const float* wk   = (const float*)d_in[4];
    const float* bk   = (const float*)d_in[5];
    const float* wv   = (const float*)d_in[6];
    const float* bv   = (const float*)d_in[7];
    const float* wo   = (const float*)d_in[8];
    const float* bo   = (const float*)d_in[9];
    const float* tb   = (const float*)d_in[10];

    void *pQ, *pK, *pV, *pCtx, *pAttnFb, *pOutFb;
    cudaGetSymbolAddress(&pQ, g_Q);
    cudaGetSymbolAddress(&pK, g_K);
    cudaGetSymbolAddress(&pV, g_V);
    cudaGetSymbolAddress(&pCtx, g_ctx);
    cudaGetSymbolAddress(&pAttnFb, g_attn_fb);
    cudaGetSymbolAddress(&pOutFb, g_out_fb);

    float* outp;
    float* attnp;
    size_t osz = (size_t)out_size;
    if (osz >= OUT_N + ATTN_N) {
        outp  = (float*)d_out;
        attnp = (float*)d_out + OUT_N;
    } else if (osz == ATTN_N) {
        attnp = (float*)d_out;
        outp  = (float*)pOutFb;
    } else {
        outp  = (float*)d_out;
        attnp = (float*)pAttnFb;
    }

    dim3 gProj(DM_ / 128, MROWS / 128);   // (8, 100)
    proj_gemm<0><<<gProj, 256>>>(x, wq, bq, (float*)pQ);
    proj_gemm<0><<<gProj, 256>>>(x, wk, bk, (float*)pK);
    proj_gemm<0><<<gProj, 256>>>(x, wv, bv, (float*)pV);

    dim3 gScore(4, 4, BH_);               // 64x64 tiles over 200x200, per (b,h)
    scores_kernel<<<gScore, 256>>>(tb, mask, attnp);

    int rows = BH_ * S_;                  // 204800 rows
    int blocks = (rows * 32 + 255) / 256; // warp per row, 8 warps/block
    softmax_kernel<<<blocks, 256>>>(attnp);

    dim3 gCtx(4, BH_);
    ctx_kernel<<<gCtx, 256>>>(attnp);

    proj_gemm<1><<<gProj, 256>>>((const float*)pCtx, wo, bo, outp);
}

// round 3
// speedup vs baseline: 1.8280x; 1.8280x over previous
#include <cuda_runtime.h>
#include <cuda_bf16.h>
#include <math.h>
#include <stdint.h>

// Problem constants
#define B_    64
#define S_    200
#define H_    16
#define DK_   64
#define DM_   1024
#define MROWS (B_ * S_)          // 12800
#define BH_   (B_ * H_)          // 1024
#define OUT_N  ((size_t)MROWS * DM_)       // 13107200
#define ATTN_N ((size_t)BH_ * S_ * S_)     // 40960000

// Scratch (allocation-free rule: __device__ globals)
__device__ float g_Q[BH_ * S_ * DK_];
__device__ float g_K[BH_ * S_ * DK_];
__device__ float g_V[BH_ * S_ * DK_];
__device__ float g_ctx[MROWS * DM_];
__device__ float g_attn_fb[BH_ * S_ * S_];
__device__ float g_out_fb[MROWS * DM_];

// ===========================================================================
// Helpers
// ===========================================================================
__device__ __forceinline__ uint32_t smem_to_u32(const void* p) {
    uint32_t a;
    asm("{ .reg .u64 t; cvta.to.shared.u64 t, %1; cvt.u32.u64 %0, t; }"
        : "=r"(a) : "l"(p));
    return a;
}

__device__ __forceinline__ void ldsm_x4(uint32_t& r0, uint32_t& r1,
                                        uint32_t& r2, uint32_t& r3, uint32_t addr) {
    asm volatile("ldmatrix.sync.aligned.m8n8.x4.shared.b16 {%0,%1,%2,%3}, [%4];"
                 : "=r"(r0), "=r"(r1), "=r"(r2), "=r"(r3) : "r"(addr));
}

__device__ __forceinline__ void mma_bf16(float* d, const uint32_t* a, const uint32_t* b) {
    asm volatile(
        "mma.sync.aligned.m16n8k16.row.col.f32.bf16.bf16.f32 "
        "{%0,%1,%2,%3}, {%4,%5,%6,%7}, {%8,%9}, {%0,%1,%2,%3};"
        : "+f"(d[0]), "+f"(d[1]), "+f"(d[2]), "+f"(d[3])
        : "r"(a[0]), "r"(a[1]), "r"(a[2]), "r"(a[3]), "r"(b[0]), "r"(b[1]));
}

#define STS128(addr, r0, r1, r2, r3) \
    asm volatile("st.shared.v4.b32 [%0], {%1,%2,%3,%4};" \
        :: "r"(addr), "r"(r0), "r"(r1), "r"(r2), "r"(r3) : "memory")

// hi/lo bf16 split of a float pair, packed as 2x uint32 (bf16x2)
__device__ __forceinline__ void split2(float x, float y, uint32_t& hi, uint32_t& lo) {
    __nv_bfloat162 h = __floats2bfloat162_rn(x, y);
    float rx = x - __bfloat162float(h.x);
    float ry = y - __bfloat162float(h.y);
    __nv_bfloat162 l = __floats2bfloat162_rn(rx, ry);
    hi = *(uint32_t*)&h;
    lo = *(uint32_t*)&l;
}

// XOR swizzle: 64-byte rows, 4 chunks of 16B; chunk ^= (row>>1)&3.
// Conflict-free for ldmatrix (8 rows same chunk) and 4-phase-floor for STS.
__device__ __forceinline__ uint32_t swz(int row, int chunk) {
    return (uint32_t)(row * 64 + ((chunk ^ ((row >> 1) & 3)) << 4));
}

// ===========================================================================
// bf16 hi/lo split GEMM via mma.sync: C[M,1024] = A[M,1024] @ W^T + bias
// CTA tile 128x128, 8 warps (2m x 4n) of 64x32, K-chunk 32, double buffer.
// OUT_MODE 0: scatter into [b,h,s,dk]. OUT_MODE 1: row-major [m,n].
// ===========================================================================
#define TILE_B     8192                // 128 rows * 64B
#define ST_AHI(s)  ((uint32_t)(s) * 32768u + 0u)
#define ST_ALO(s)  ((uint32_t)(s) * 32768u + 8192u)
#define ST_BHI(s)  ((uint32_t)(s) * 32768u + 16384u)
#define ST_BLO(s)  ((uint32_t)(s) * 32768u + 24576u)
#define GEMM_SMEM  65536

__device__ __forceinline__ void cvt_store16(uint32_t base_hi, uint32_t base_lo,
                                            int row, int chunk0, const float4* f) {
    uint32_t h[8], l[8];
    split2(f[0].x, f[0].y, h[0], l[0]); split2(f[0].z, f[0].w, h[1], l[1]);
    split2(f[1].x, f[1].y, h[2], l[2]); split2(f[1].z, f[1].w, h[3], l[3]);
    split2(f[2].x, f[2].y, h[4], l[4]); split2(f[2].z, f[2].w, h[5], l[5]);
    split2(f[3].x, f[3].y, h[6], l[6]); split2(f[3].z, f[3].w, h[7], l[7]);
    uint32_t s0 = swz(row, chunk0), s1 = swz(row, chunk0 + 1);
    STS128(base_hi + s0, h[0], h[1], h[2], h[3]);
    STS128(base_hi + s1, h[4], h[5], h[6], h[7]);
    STS128(base_lo + s0, l[0], l[1], l[2], l[3]);
    STS128(base_lo + s1, l[4], l[5], l[6], l[7]);
}

template <int OUT_MODE>
__global__ void __launch_bounds__(256, 1) gemm_mma(
    const float* __restrict__ A, const float* __restrict__ W,
    const float* __restrict__ bias, float* __restrict__ C)
{
    extern __shared__ char smem[];
    const uint32_t sb = smem_to_u32(smem);
    const int tid  = threadIdx.x;
    const int lane = tid & 31;
    const int wid  = tid >> 5;
    const int wm   = wid >> 2;     // 0..1
    const int wn   = wid & 3;      // 0..3
    const int m0   = blockIdx.y * 128;
    const int n0   = blockIdx.x * 128;

    const int lrow  = tid >> 1;    // 0..127
    const int lhalf = tid & 1;     // 0..1  (16-float half of the 32-float row chunk)

    const float* Ag = A + (size_t)(m0 + lrow) * DM_ + lhalf * 16;
    const float* Bg = W + (size_t)(n0 + lrow) * DM_ + lhalf * 16;

    float acc[4][4][4];
#pragma unroll
    for (int i = 0; i < 4; i++)
#pragma unroll
        for (int j = 0; j < 4; j++)
#pragma unroll
            for (int r = 0; r < 4; r++) acc[i][j][r] = 0.f;

    // Prologue: stage 0
    float4 pa[4], pb[4];
#pragma unroll
    for (int i = 0; i < 4; i++) {
        pa[i] = *(const float4*)(Ag + i * 4);
        pb[i] = *(const float4*)(Bg + i * 4);
    }
    cvt_store16(sb + ST_AHI(0), sb + ST_ALO(0), lrow, lhalf * 2, pa);
    cvt_store16(sb + ST_BHI(0), sb + ST_BLO(0), lrow, lhalf * 2, pb);
    __syncthreads();

    // ldmatrix lane mappings (constant per thread)
    const int a_row_in = lane & 15;          // row within m16 tile
    const int a_kh     = lane >> 4;          // 0/1 -> k chunk half
    const int b_col_in = (lane & 7) + ((lane >> 4) << 3);  // col within n16
    const int b_kh     = (lane >> 3) & 1;

    for (int kt = 0; kt < 32; kt++) {
        const int cur = kt & 1;

        if (kt < 31) {
#pragma unroll
            for (int i = 0; i < 4; i++) {
                pa[i] = *(const float4*)(Ag + (kt + 1) * 32 + i * 4);
                pb[i] = *(const float4*)(Bg + (kt + 1) * 32 + i * 4);
            }
        }

        const uint32_t ahiB = sb + ST_AHI(cur), aloB = sb + ST_ALO(cur);
        const uint32_t bhiB = sb + ST_BHI(cur), bloB = sb + ST_BLO(cur);

#pragma unroll
        for (int ks = 0; ks < 2; ks++) {
            uint32_t ahi[4][4], alo[4][4];
#pragma unroll
            for (int mf = 0; mf < 4; mf++) {
                int row = wm * 64 + mf * 16 + a_row_in;
                int ch  = ks * 2 + a_kh;
                uint32_t so = swz(row, ch);
                ldsm_x4(ahi[mf][0], ahi[mf][1], ahi[mf][2], ahi[mf][3], ahiB + so);
                ldsm_x4(alo[mf][0], alo[mf][1], alo[mf][2], alo[mf][3], aloB + so);
            }
            uint32_t bhi[4][2], blo[4][2];
#pragma unroll
            for (int bi = 0; bi < 2; bi++) {
                int col = wn * 32 + bi * 16 + b_col_in;
                int ch  = ks * 2 + b_kh;
                uint32_t so = swz(col, ch);
                uint32_t r0, r1, r2, r3;
                ldsm_x4(r0, r1, r2, r3, bhiB + so);
                bhi[bi * 2][0] = r0; bhi[bi * 2][1] = r1;
                bhi[bi * 2 + 1][0] = r2; bhi[bi * 2 + 1][1] = r3;
                ldsm_x4(r0, r1, r2, r3, bloB + so);
                blo[bi * 2][0] = r0; blo[bi * 2][1] = r1;
                blo[bi * 2 + 1][0] = r2; blo[bi * 2 + 1][1] = r3;
            }
#pragma unroll
            for (int mf = 0; mf < 4; mf++)
#pragma unroll
                for (int nf = 0; nf < 4; nf++) {
                    mma_bf16(acc[mf][nf], ahi[mf], bhi[nf]);
                    mma_bf16(acc[mf][nf], ahi[mf], blo[nf]);
                    mma_bf16(acc[mf][nf], alo[mf], bhi[nf]);
                }
        }
        __syncthreads();
        if (kt < 31) {
            const int nxt = (kt + 1) & 1;
            cvt_store16(sb + ST_AHI(nxt), sb + ST_ALO(nxt), lrow, lhalf * 2, pa);
            cvt_store16(sb + ST_BHI(nxt), sb + ST_BLO(nxt), lrow, lhalf * 2, pb);
            __syncthreads();
        }
    }

    // Epilogue: D frag thread mapping m16n8: row g=lane>>2 (+8), col (lane&3)*2 (+1)
    const int g  = lane >> 2;
    const int c2 = (lane & 3) * 2;
#pragma unroll
    for (int nf = 0; nf < 4; nf++) {
        const int n = n0 + wn * 32 + nf * 8 + c2;
        const float b0 = bias[n], b1 = bias[n + 1];
#pragma unroll
        for (int mf = 0; mf < 4; mf++) {
            const int m = m0 + wm * 64 + mf * 16 + g;
            float2 v0 = make_float2(acc[mf][nf][0] + b0, acc[mf][nf][1] + b1);
            float2 v1 = make_float2(acc[mf][nf][2] + b0, acc[mf][nf][3] + b1);
            if (OUT_MODE == 0) {
                int bb = m / S_;
                int ss = m - bb * S_;
                int hh = n >> 6;
                int dk = n & 63;
                float* base = C + (((size_t)bb * H_ + hh) * S_) * DK_ + dk;
                *(float2*)(base + (size_t)ss * DK_)       = v0;
                int m2 = m + 8;
                int bb2 = m2 / S_;
                int ss2 = m2 - bb2 * S_;
                float* base2 = C + (((size_t)bb2 * H_ + hh) * S_) * DK_ + dk;
                *(float2*)(base2 + (size_t)ss2 * DK_)     = v1;
            } else {
                *(float2*)(C + (size_t)m * DM_ + n)       = v0;
                *(float2*)(C + (size_t)(m + 8) * DM_ + n) = v1;
            }
        }
    }
}

// ---------------------------------------------------------------------------
// Scores: attn[bh,i,j] = Q[bh,i,:]·K[bh,j,:] / 8 + bias[h,i,j], masked.
// ---------------------------------------------------------------------------
__global__ void __launch_bounds__(256) scores_kernel(
    const float* __restrict__ tb, const int* __restrict__ mask,
    float* __restrict__ attn)
{
    const int bh = blockIdx.z;
    const int b  = bh >> 4;
    const int h  = bh & 15;
    const int i0 = blockIdx.y * 64;
    const int j0 = blockIdx.x * 64;

    const float* Q = g_Q + (size_t)bh * S_ * DK_;
    const float* K = g_K + (size_t)bh * S_ * DK_;

    __shared__ float Qs[64][65];
    __shared__ float Ks[64][65];

    const int tid = threadIdx.x;
    const int r   = tid >> 4;
    const int c4  = (tid & 15) << 2;

#pragma unroll
    for (int it = 0; it < 4; it++) {
        int row = r + it * 16;
        int gi = i0 + row, gj = j0 + row;
        float4 vq = make_float4(0.f, 0.f, 0.f, 0.f);
        float4 vk = make_float4(0.f, 0.f, 0.f, 0.f);
        if (gi < S_) vq = *(const float4*)&Q[(size_t)gi * DK_ + c4];
        if (gj < S_) vk = *(const float4*)&K[(size_t)gj * DK_ + c4];
        Qs[c4 + 0][row] = vq.x; Qs[c4 + 1][row] = vq.y;
        Qs[c4 + 2][row] = vq.z; Qs[c4 + 3][row] = vq.w;
        Ks[c4 + 0][row] = vk.x; Ks[c4 + 1][row] = vk.y;
        Ks[c4 + 2][row] = vk.z; Ks[c4 + 3][row] = vk.w;
    }
    __syncthreads();

    const int tx = tid & 15, ty = tid >> 4;
    float acc[4][4];
#pragma unroll
    for (int i = 0; i < 4; i++)
#pragma unroll
        for (int j = 0; j < 4; j++) acc[i][j] = 0.f;

#pragma unroll 8
    for (int k = 0; k < 64; k++) {
        float ra[4], rb[4];
#pragma unroll
        for (int ii = 0; ii < 4; ii++) ra[ii] = Qs[k][ty * 4 + ii];
#pragma unroll
        for (int jj = 0; jj < 4; jj++) rb[jj] = Ks[k][tx * 4 + jj];
#pragma unroll
        for (int ii = 0; ii < 4; ii++)
#pragma unroll
            for (int jj = 0; jj < 4; jj++)
                acc[ii][jj] = fmaf(ra[ii], rb[jj], acc[ii][jj]);
    }

    const float* tbh  = tb + (size_t)h * S_ * S_;
    const int*   mb   = mask + (size_t)b * S_ * S_;
    float*       outp = attn + (size_t)bh * S_ * S_;

#pragma unroll
    for (int ii = 0; ii < 4; ii++) {
        int gi = i0 + ty * 4 + ii;
        if (gi >= S_) continue;
#pragma unroll
        for (int jj = 0; jj < 4; jj++) {
            int gj = j0 + tx * 4 + jj;
            if (gj >= S_) continue;
            float v = acc[ii][jj] * 0.125f + tbh[gi * S_ + gj];
            if (mb[gi * S_ + gj] == 0) v = -1e9f;
            outp[gi * S_ + gj] = v;
        }
    }
}

// ---------------------------------------------------------------------------
// Row softmax in place (warp per row of length 200)
// ---------------------------------------------------------------------------
__global__ void __launch_bounds__(256) softmax_kernel(float* __restrict__ attn)
{
    const int gwarp = (blockIdx.x * blockDim.x + threadIdx.x) >> 5;
    const int lane  = threadIdx.x & 31;
    if (gwarp >= BH_ * S_) return;
    float* row = attn + (size_t)gwarp * S_;

    float v[7];
    float mx = -1e30f;
#pragma unroll
    for (int t = 0; t < 7; t++) {
        int j = lane + t * 32;
        v[t] = (j < S_) ? row[j] : -1e30f;
        mx = fmaxf(mx, v[t]);
    }
#pragma unroll
    for (int o = 16; o > 0; o >>= 1) mx = fmaxf(mx, __shfl_xor_sync(0xffffffffu, mx, o));

    float sum = 0.f;
#pragma unroll
    for (int t = 0; t < 7; t++) {
        int j = lane + t * 32;
        v[t] = (j < S_) ? expf(v[t] - mx) : 0.f;
        sum += v[t];
    }
#pragma unroll
    for (int o = 16; o > 0; o >>= 1) sum += __shfl_xor_sync(0xffffffffu, sum, o);

    const float inv = 1.f / sum;
#pragma unroll
    for (int t = 0; t < 7; t++) {
        int j = lane + t * 32;
        if (j < S_) row[j] = v[t] * inv;
    }
}

// ---------------------------------------------------------------------------
// ctx[b,s,h*64+dk] = sum_j attn[bh,s,j] * V[bh,j,dk]
// ---------------------------------------------------------------------------
__global__ void __launch_bounds__(256) ctx_kernel(const float* __restrict__ attn)
{
    const int bh = blockIdx.y;
    const int b  = bh >> 4;
    const int h  = bh & 15;
    const int i0 = blockIdx.x * 64;

    const float* Arow = attn + (size_t)bh * S_ * S_;
    const float* V    = g_V  + (size_t)bh * S_ * DK_;

    __shared__ float As[8][65];
    __shared__ float Vs[8][64];

    const int tid = threadIdx.x;
    const int tx = tid & 15, ty = tid >> 4;

    float acc[4][4];
#pragma unroll
    for (int i = 0; i < 4; i++)
#pragma unroll
        for (int j = 0; j < 4; j++) acc[i][j] = 0.f;

    const int ai = tid >> 2;
    const int ak = (tid & 3) << 1;
    const int vk = tid >> 5;
    const int vd = (tid & 31) << 1;

    for (int k0 = 0; k0 < S_; k0 += 8) {
        int gi = i0 + ai;
        float2 va = make_float2(0.f, 0.f);
        if (gi < S_) va = *(const float2*)&Arow[(size_t)gi * S_ + k0 + ak];
        As[ak][ai] = va.x; As[ak + 1][ai] = va.y;

        float2 vv = *(const float2*)&V[(size_t)(k0 + vk) * DK_ + vd];
        *(float2*)&Vs[vk][vd] = vv;
        __syncthreads();

#pragma unroll
        for (int k = 0; k < 8; k++) {
            float ra[4], rb[4];
#pragma unroll
            for (int ii = 0; ii < 4; ii++) ra[ii] = As[k][ty * 4 + ii];
            *(float4*)&rb[0] = *(const float4*)&Vs[k][tx * 4];
#pragma unroll
            for (int ii = 0; ii < 4; ii++)
#pragma unroll
                for (int jj = 0; jj < 4; jj++)
                    acc[ii][jj] = fmaf(ra[ii], rb[jj], acc[ii][jj]);
        }
        __syncthreads();
    }

#pragma unroll
    for (int ii = 0; ii < 4; ii++) {
        int ss = i0 + ty * 4 + ii;
        if (ss >= S_) continue;
        float* dst = g_ctx + ((size_t)b * S_ + ss) * DM_ + h * DK_ + tx * 4;
        *(float4*)dst = *(float4*)&acc[ii][0];
    }
}

// ---------------------------------------------------------------------------
extern "C" void kernel_launch(void* const* d_in, const int* in_sizes, int n_in,
                              void* d_out, int out_size)
{
    const float* x    = (const float*)d_in[0];
    const int*   mask = (const int*)  d_in[1];
    const float* wq   = (const float*)d_in[2];
    const float* bq   = (const float*)d_in[3];
    const float* wk   = (const float*)d_in[4];
    const float* bk   = (const float*)d_in[5];
    const float* wv   = (const float*)d_in[6];
    const float* bv   = (const float*)d_in[7];
    const float* wo   = (const float*)d_in[8];
    const float* bo   = (const float*)d_in[9];
    const float* tb   = (const float*)d_in[10];

    void *pQ, *pK, *pV, *pCtx, *pAttnFb, *pOutFb;
    cudaGetSymbolAddress(&pQ, g_Q);
    cudaGetSymbolAddress(&pK, g_K);
    cudaGetSymbolAddress(&pV, g_V);
    cudaGetSymbolAddress(&pCtx, g_ctx);
    cudaGetSymbolAddress(&pAttnFb, g_attn_fb);
    cudaGetSymbolAddress(&pOutFb, g_out_fb);

    float* outp;
    float* attnp;
    size_t osz = (size_t)out_size;
    if (osz >= OUT_N + ATTN_N) {
        outp  = (float*)d_out;
        attnp = (float*)d_out + OUT_N;
    } else if (osz == ATTN_N) {
        attnp = (float*)d_out;
        outp  = (float*)pOutFb;
    } else {
        outp  = (float*)d_out;
        attnp = (float*)pAttnFb;
    }

    cudaFuncSetAttribute(gemm_mma<0>, cudaFuncAttributeMaxDynamicSharedMemorySize, GEMM_SMEM);
    cudaFuncSetAttribute(gemm_mma<1>, cudaFuncAttributeMaxDynamicSharedMemorySize, GEMM_SMEM);

    dim3 gProj(DM_ / 128, MROWS / 128);   // (8, 100)
    gemm_mma<0><<<gProj, 256, GEMM_SMEM>>>(x, wq, bq, (float*)pQ);
    gemm_mma<0><<<gProj, 256, GEMM_SMEM>>>(x, wk, bk, (float*)pK);
    gemm_mma<0><<<gProj, 256, GEMM_SMEM>>>(x, wv, bv, (float*)pV);

    dim3 gScore(4, 4, BH_);
    scores_kernel<<<gScore, 256>>>(tb, mask, attnp);

    int rows = BH_ * S_;
    int blocks = (rows * 32 + 255) / 256;
    softmax_kernel<<<blocks, 256>>>(attnp);

    dim3 gCtx(4, BH_);
    ctx_kernel<<<gCtx, 256>>>(attnp);

    gemm_mma<1><<<gProj, 256, GEMM_SMEM>>>((const float*)pCtx, wo, bo, outp);
}

// round 4
// speedup vs baseline: 1.9750x; 1.0804x over previous
#include <cuda_runtime.h>
#include <cuda_bf16.h>
#include <math.h>
#include <stdint.h>

// Problem constants
#define B_    64
#define S_    200
#define H_    16
#define DK_   64
#define DM_   1024
#define MROWS (B_ * S_)          // 12800
#define BH_   (B_ * H_)          // 1024
#define OUT_N  ((size_t)MROWS * DM_)       // 13107200
#define ATTN_N ((size_t)BH_ * S_ * S_)     // 40960000

// Scratch (allocation-free rule: __device__ globals)
__device__ float g_Q[BH_ * S_ * DK_];
__device__ float g_K[BH_ * S_ * DK_];
__device__ float g_V[BH_ * S_ * DK_];
__device__ float g_ctx[MROWS * DM_];
__device__ float g_attn_fb[BH_ * S_ * S_];
__device__ float g_out_fb[MROWS * DM_];

// ===========================================================================
// Helpers
// ===========================================================================
__device__ __forceinline__ uint32_t smem_to_u32(const void* p) {
    uint32_t a;
    asm("{ .reg .u64 t; cvta.to.shared.u64 t, %1; cvt.u32.u64 %0, t; }"
        : "=r"(a) : "l"(p));
    return a;
}

__device__ __forceinline__ void ldsm_x4(uint32_t& r0, uint32_t& r1,
                                        uint32_t& r2, uint32_t& r3, uint32_t addr) {
    asm volatile("ldmatrix.sync.aligned.m8n8.x4.shared.b16 {%0,%1,%2,%3}, [%4];"
                 : "=r"(r0), "=r"(r1), "=r"(r2), "=r"(r3) : "r"(addr));
}
__device__ __forceinline__ void ldsm_x4_t(uint32_t& r0, uint32_t& r1,
                                          uint32_t& r2, uint32_t& r3, uint32_t addr) {
    asm volatile("ldmatrix.sync.aligned.m8n8.x4.trans.shared.b16 {%0,%1,%2,%3}, [%4];"
                 : "=r"(r0), "=r"(r1), "=r"(r2), "=r"(r3) : "r"(addr));
}

__device__ __forceinline__ void mma_bf16(float* d, const uint32_t* a, const uint32_t* b) {
    asm volatile(
        "mma.sync.aligned.m16n8k16.row.col.f32.bf16.bf16.f32 "
        "{%0,%1,%2,%3}, {%4,%5,%6,%7}, {%8,%9}, {%0,%1,%2,%3};"
        : "+f"(d[0]), "+f"(d[1]), "+f"(d[2]), "+f"(d[3])
        : "r"(a[0]), "r"(a[1]), "r"(a[2]), "r"(a[3]), "r"(b[0]), "r"(b[1]));
}

#define STS128(addr, r0, r1, r2, r3) \
    asm volatile("st.shared.v4.b32 [%0], {%1,%2,%3,%4};" \
        :: "r"(addr), "r"(r0), "r"(r1), "r"(r2), "r"(r3) : "memory")
#define STS64_U(addr, val) \
    asm volatile("st.shared.b64 [%0], %1;" :: "r"(addr), "l"(val) : "memory")

// hi/lo bf16 split of a float pair, packed as 2x uint32 (bf16x2)
__device__ __forceinline__ void split2(float x, float y, uint32_t& hi, uint32_t& lo) {
    __nv_bfloat162 h = __floats2bfloat162_rn(x, y);
    float rx = x - __bfloat162float(h.x);
    float ry = y - __bfloat162float(h.y);
    __nv_bfloat162 l = __floats2bfloat162_rn(rx, ry);
    hi = *(uint32_t*)&h;
    lo = *(uint32_t*)&l;
}

// 64B-row swizzle (gemm kernel): 4 chunks of 16B; chunk ^= (row>>1)&3
__device__ __forceinline__ uint32_t swz(int row, int chunk) {
    return (uint32_t)(row * 64 + ((chunk ^ ((row >> 1) & 3)) << 4));
}
// 128B-row swizzle (attention kernel): 8 chunks of 16B; chunk ^= row&7
__device__ __forceinline__ uint32_t swz128(int row, int chunk) {
    return (uint32_t)(row * 128 + ((chunk ^ (row & 7)) << 4));
}

// ===========================================================================
// bf16 hi/lo split GEMM via mma.sync: C[M,1024] = A[M,1024] @ W^T + bias
// CTA tile 128x128, 8 warps (2m x 4n) of 64x32, K-chunk 32, double buffer.
// OUT_MODE 0: scatter into [b,h,s,dk]. OUT_MODE 1: row-major [m,n].
// ===========================================================================
#define ST_AHI(s)  ((uint32_t)(s) * 32768u + 0u)
#define ST_ALO(s)  ((uint32_t)(s) * 32768u + 8192u)
#define ST_BHI(s)  ((uint32_t)(s) * 32768u + 16384u)
#define ST_BLO(s)  ((uint32_t)(s) * 32768u + 24576u)
#define GEMM_SMEM  65536

__device__ __forceinline__ void cvt_store16(uint32_t base_hi, uint32_t base_lo,
                                            int row, int chunk0, const float4* f) {
    uint32_t h[8], l[8];
    split2(f[0].x, f[0].y, h[0], l[0]); split2(f[0].z, f[0].w, h[1], l[1]);
    split2(f[1].x, f[1].y, h[2], l[2]); split2(f[1].z, f[1].w, h[3], l[3]);
    split2(f[2].x, f[2].y, h[4], l[4]); split2(f[2].z, f[2].w, h[5], l[5]);
    split2(f[3].x, f[3].y, h[6], l[6]); split2(f[3].z, f[3].w, h[7], l[7]);
    uint32_t s0 = swz(row, chunk0), s1 = swz(row, chunk0 + 1);
    STS128(base_hi + s0, h[0], h[1], h[2], h[3]);
    STS128(base_hi + s1, h[4], h[5], h[6], h[7]);
    STS128(base_lo + s0, l[0], l[1], l[2], l[3]);
    STS128(base_lo + s1, l[4], l[5], l[6], l[7]);
}

template <int OUT_MODE>
__global__ void __launch_bounds__(256, 1) gemm_mma(
    const float* __restrict__ A, const float* __restrict__ W,
    const float* __restrict__ bias, float* __restrict__ C)
{
    extern __shared__ char smem[];
    const uint32_t sb = smem_to_u32(smem);
    const int tid  = threadIdx.x;
    const int lane = tid & 31;
    const int wid  = tid >> 5;
    const int wm   = wid >> 2;
    const int wn   = wid & 3;
    const int m0   = blockIdx.y * 128;
    const int n0   = blockIdx.x * 128;

    const int lrow  = tid >> 1;
    const int lhalf = tid & 1;

    const float* Ag = A + (size_t)(m0 + lrow) * DM_ + lhalf * 16;
    const float* Bg = W + (size_t)(n0 + lrow) * DM_ + lhalf * 16;

    float acc[4][4][4];
#pragma unroll
    for (int i = 0; i < 4; i++)
#pragma unroll
        for (int j = 0; j < 4; j++)
#pragma unroll
            for (int r = 0; r < 4; r++) acc[i][j][r] = 0.f;

    float4 pa[4], pb[4];
#pragma unroll
    for (int i = 0; i < 4; i++) {
        pa[i] = *(const float4*)(Ag + i * 4);
        pb[i] = *(const float4*)(Bg + i * 4);
    }
    cvt_store16(sb + ST_AHI(0), sb + ST_ALO(0), lrow, lhalf * 2, pa);
    cvt_store16(sb + ST_BHI(0), sb + ST_BLO(0), lrow, lhalf * 2, pb);
    __syncthreads();

    const int a_row_in = lane & 15;
    const int a_kh     = lane >> 4;
    const int b_col_in = (lane & 7) + ((lane >> 4) << 3);
    const int b_kh     = (lane >> 3) & 1;

    for (int kt = 0; kt < 32; kt++) {
        const int cur = kt & 1;

        if (kt < 31) {
#pragma unroll
            for (int i = 0; i < 4; i++) {
                pa[i] = *(const float4*)(Ag + (kt + 1) * 32 + i * 4);
                pb[i] = *(const float4*)(Bg + (kt + 1) * 32 + i * 4);
            }
        }

        const uint32_t ahiB = sb + ST_AHI(cur), aloB = sb + ST_ALO(cur);
        const uint32_t bhiB = sb + ST_BHI(cur), bloB = sb + ST_BLO(cur);

#pragma unroll
        for (int ks = 0; ks < 2; ks++) {
            uint32_t ahi[4][4], alo[4][4];
#pragma unroll
            for (int mf = 0; mf < 4; mf++) {
                int row = wm * 64 + mf * 16 + a_row_in;
                int ch  = ks * 2 + a_kh;
                uint32_t so = swz(row, ch);
                ldsm_x4(ahi[mf][0], ahi[mf][1], ahi[mf][2], ahi[mf][3], ahiB + so);
                ldsm_x4(alo[mf][0], alo[mf][1], alo[mf][2], alo[mf][3], aloB + so);
            }
            uint32_t bhi[4][2], blo[4][2];
#pragma unroll
            for (int bi = 0; bi < 2; bi++) {
                int col = wn * 32 + bi * 16 + b_col_in;
                int ch  = ks * 2 + b_kh;
                uint32_t so = swz(col, ch);
                uint32_t r0, r1, r2, r3;
                ldsm_x4(r0, r1, r2, r3, bhiB + so);
                bhi[bi * 2][0] = r0; bhi[bi * 2][1] = r1;
                bhi[bi * 2 + 1][0] = r2; bhi[bi * 2 + 1][1] = r3;
                ldsm_x4(r0, r1, r2, r3, bloB + so);
                blo[bi * 2][0] = r0; blo[bi * 2][1] = r1;
                blo[bi * 2 + 1][0] = r2; blo[bi * 2 + 1][1] = r3;
            }
#pragma unroll
            for (int mf = 0; mf < 4; mf++)
#pragma unroll
                for (int nf = 0; nf < 4; nf++) {
                    mma_bf16(acc[mf][nf], ahi[mf], bhi[nf]);
                    mma_bf16(acc[mf][nf], ahi[mf], blo[nf]);
                    mma_bf16(acc[mf][nf], alo[mf], bhi[nf]);
                }
        }
        __syncthreads();
        if (kt < 31) {
            const int nxt = (kt + 1) & 1;
            cvt_store16(sb + ST_AHI(nxt), sb + ST_ALO(nxt), lrow, lhalf * 2, pa);
            cvt_store16(sb + ST_BHI(nxt), sb + ST_BLO(nxt), lrow, lhalf * 2, pb);
            __syncthreads();
        }
    }

    const int g  = lane >> 2;
    const int c2 = (lane & 3) * 2;
#pragma unroll
    for (int nf = 0; nf < 4; nf++) {
        const int n = n0 + wn * 32 + nf * 8 + c2;
        const float b0 = bias[n], b1 = bias[n + 1];
#pragma unroll
        for (int mf = 0; mf < 4; mf++) {
            const int m = m0 + wm * 64 + mf * 16 + g;
            float2 v0 = make_float2(acc[mf][nf][0] + b0, acc[mf][nf][1] + b1);
            float2 v1 = make_float2(acc[mf][nf][2] + b0, acc[mf][nf][3] + b1);
            if (OUT_MODE == 0) {
                int bb = m / S_;
                int ss = m - bb * S_;
                int hh = n >> 6;
                int dk = n & 63;
                float* base = C + (((size_t)bb * H_ + hh) * S_) * DK_ + dk;
                *(float2*)(base + (size_t)ss * DK_)       = v0;
                int m2 = m + 8;
                int bb2 = m2 / S_;
                int ss2 = m2 - bb2 * S_;
                float* base2 = C + (((size_t)bb2 * H_ + hh) * S_) * DK_ + dk;
                *(float2*)(base2 + (size_t)ss2 * DK_)     = v1;
            } else {
                *(float2*)(C + (size_t)m * DM_ + n)       = v0;
                *(float2*)(C + (size_t)(m + 8) * DM_ + n) = v1;
            }
        }
    }
}

// ===========================================================================
// Fused attention: per CTA = (q-tile of 64 rows, bh). 128 threads, 4 warps.
// scores = Q·K^T (bf16 hi/lo mma) -> scale+bias+mask+softmax in regs ->
// attn written to gmem, acc frags repacked as A frags -> ctx = attn·V (mma).
// ===========================================================================
#define FA_QHI  0u
#define FA_QLO  8192u
#define FA_KHI  16384u
#define FA_KLO  43008u
#define FA_VHI  69632u
#define FA_VLO  96256u
#define FA_SMEM 122880

__device__ __forceinline__ void fa_sts(uint32_t hiB, uint32_t loB,
                                       int r, int c4, float4 v) {
    uint32_t h0, l0, h1, l1;
    split2(v.x, v.y, h0, l0);
    split2(v.z, v.w, h1, l1);
    uint32_t addr = (uint32_t)(r * 128 + (((c4 >> 1) ^ (r & 7)) << 4) + ((c4 & 1) << 3));
    STS64_U(hiB + addr, (uint64_t)h0 | ((uint64_t)h1 << 32));
    STS64_U(loB + addr, (uint64_t)l0 | ((uint64_t)l1 << 32));
}

__global__ void __launch_bounds__(128, 1) attn_fused(
    const int* __restrict__ mask, float* __restrict__ attn)
{
    extern __shared__ char smem[];
    const uint32_t sb = smem_to_u32(smem);
    const int tid  = threadIdx.x;
    const int lane = tid & 31;
    const int w    = tid >> 5;
    const int qt   = blockIdx.x;          // 0..3
    const int bh   = blockIdx.y;
    const int b    = bh >> 4;

    const float* Qg = g_Q + (size_t)bh * S_ * DK_;
    const float* Kg = g_K + (size_t)bh * S_ * DK_;
    const float* Vg = g_V + (size_t)bh * S_ * DK_;

    // ---- Load Q (64x64), K (200x64), V (200x64) as bf16 hi/lo into smem ----
#pragma unroll
    for (int t = 0; t < 8; t++) {
        int u = tid + t * 128;
        int r = u >> 4, c4 = u & 15;
        int gi = qt * 64 + r;
        float4 v = make_float4(0.f, 0.f, 0.f, 0.f);
        if (gi < S_) v = *(const float4*)(Qg + (size_t)gi * DK_ + c4 * 4);
        fa_sts(sb + FA_QHI, sb + FA_QLO, r, c4, v);
    }
#pragma unroll
    for (int t = 0; t < 25; t++) {
        int u = tid + t * 128;
        int r = u >> 4, c4 = u & 15;
        float4 vk = *(const float4*)(Kg + (size_t)r * DK_ + c4 * 4);
        float4 vv = *(const float4*)(Vg + (size_t)r * DK_ + c4 * 4);
        fa_sts(sb + FA_KHI, sb + FA_KLO, r, c4, vk);
        fa_sts(sb + FA_VHI, sb + FA_VLO, r, c4, vv);
    }
    {   // zero-pad rows 200..207 of K and V
        int r = 200 + (tid >> 4), c4 = tid & 15;
        uint32_t addr = (uint32_t)(r * 128 + (((c4 >> 1) ^ (r & 7)) << 4) + ((c4 & 1) << 3));
        STS64_U(sb + FA_KHI + addr, 0ull);
        STS64_U(sb + FA_KLO + addr, 0ull);
        STS64_U(sb + FA_VHI + addr, 0ull);
        STS64_U(sb + FA_VLO + addr, 0ull);
    }
    __syncthreads();

    // ---- Scores: acc[25 n8-frags][4] over k=64 (4 k16 steps, 3 passes) ----
    float acc[25][4];
#pragma unroll
    for (int f = 0; f < 25; f++)
#pragma unroll
        for (int r = 0; r < 4; r++) acc[f][r] = 0.f;

    const int a_row_in = lane & 15;
    const int a_kh     = lane >> 4;
    const int b_col_in = (lane & 7) + ((lane >> 4) << 3);
    const int b_kh     = (lane >> 3) & 1;

    for (int kb = 0; kb < 4; kb++) {
        uint32_t ahi[4], alo[4];
        {
            int row = w * 16 + a_row_in;
            int ch  = kb * 2 + a_kh;
            uint32_t so = swz128(row, ch);
            ldsm_x4(ahi[0], ahi[1], ahi[2], ahi[3], sb + FA_QHI + so);
            ldsm_x4(alo[0], alo[1], alo[2], alo[3], sb + FA_QLO + so);
        }
#pragma unroll
        for (int nb = 0; nb < 13; nb++) {
            int row = nb * 16 + b_col_in;
            int ch  = kb * 2 + b_kh;
            uint32_t so = swz128(row, ch);
            uint32_t h0, h1, h2, h3, l0, l1, l2, l3;
            ldsm_x4(h0, h1, h2, h3, sb + FA_KHI + so);
            ldsm_x4(l0, l1, l2, l3, sb + FA_KLO + so);
            uint32_t bh0[2] = {h0, h1}, bl0[2] = {l0, l1};
            mma_bf16(acc[nb * 2], ahi, bh0);
            mma_bf16(acc[nb * 2], ahi, bl0);
            mma_bf16(acc[nb * 2], alo, bh0);
            if (nb < 12) {
                uint32_t bh1[2] = {h2, h3}, bl1[2] = {l2, l3};
                mma_bf16(acc[nb * 2 + 1], ahi, bh1);
                mma_bf16(acc[nb * 2 + 1], ahi, bl1);
                mma_bf16(acc[nb * 2 + 1], alo, bh1);
            }
        }
    }

    // ---- Epilogue: scale + temporal bias + mask, softmax in registers ----
    const int g  = lane >> 2;
    const int c2 = (lane & 3) * 2;
    const int gi0 = qt * 64 + w * 16 + g;
    const int gi1 = gi0 + 8;
    const bool v0ok = (gi0 < S_);
    const bool v1ok = (gi1 < S_);
    const int* mrow0 = mask + (size_t)b * S_ * S_ + (size_t)gi0 * S_;
    const int* mrow1 = mask + (size_t)b * S_ * S_ + (size_t)gi1 * S_;
    const float BC = -0.1f / 200.0f;

    float mx0 = -1e30f, mx1 = -1e30f;
#pragma unroll
    for (int f = 0; f < 25; f++) {
        int gj = f * 8 + c2;
        int2 m0 = v0ok ? *(const int2*)(mrow0 + gj) : make_int2(1, 1);
        int2 m1 = v1ok ? *(const int2*)(mrow1 + gj) : make_int2(1, 1);
        float t00 = BC * fabsf((float)(gi0 - gj));
        float t01 = BC * fabsf((float)(gi0 - gj - 1));
        float t10 = BC * fabsf((float)(gi1 - gj));
        float t11 = BC * fabsf((float)(gi1 - gj - 1));
        acc[f][0] = (m0.x == 0) ? -1e9f : fmaf(acc[f][0], 0.125f, t00);
        acc[f][1] = (m0.y == 0) ? -1e9f : fmaf(acc[f][1], 0.125f, t01);
        acc[f][2] = (m1.x == 0) ? -1e9f : fmaf(acc[f][2], 0.125f, t10);
        acc[f][3] = (m1.y == 0) ? -1e9f : fmaf(acc[f][3], 0.125f, t11);
        mx0 = fmaxf(mx0, fmaxf(acc[f][0], acc[f][1]));
        mx1 = fmaxf(mx1, fmaxf(acc[f][2], acc[f][3]));
    }
    mx0 = fmaxf(mx0, __shfl_xor_sync(0xffffffffu, mx0, 1));
    mx0 = fmaxf(mx0, __shfl_xor_sync(0xffffffffu, mx0, 2));
    mx1 = fmaxf(mx1, __shfl_xor_sync(0xffffffffu, mx1, 1));
    mx1 = fmaxf(mx1, __shfl_xor_sync(0xffffffffu, mx1, 2));

    float s0 = 0.f, s1 = 0.f;
#pragma unroll
    for (int f = 0; f < 25; f++) {
        acc[f][0] = expf(acc[f][0] - mx0);
        acc[f][1] = expf(acc[f][1] - mx0);
        acc[f][2] = expf(acc[f][2] - mx1);
        acc[f][3] = expf(acc[f][3] - mx1);
        s0 += acc[f][0] + acc[f][1];
        s1 += acc[f][2] + acc[f][3];
    }
    s0 += __shfl_xor_sync(0xffffffffu, s0, 1);
    s0 += __shfl_xor_sync(0xffffffffu, s0, 2);
    s1 += __shfl_xor_sync(0xffffffffu, s1, 1);
    s1 += __shfl_xor_sync(0xffffffffu, s1, 2);
    const float i0 = 1.f / s0;
    const float i1 = 1.f / s1;

    float* arow0 = attn + (size_t)bh * S_ * S_ + (size_t)gi0 * S_;
    float* arow1 = attn + (size_t)bh * S_ * S_ + (size_t)gi1 * S_;
#pragma unroll
    for (int f = 0; f < 25; f++) {
        int gj = f * 8 + c2;
        acc[f][0] *= i0; acc[f][1] *= i0;
        acc[f][2] *= i1; acc[f][3] *= i1;
        if (v0ok) *(float2*)(arow0 + gj) = make_float2(acc[f][0], acc[f][1]);
        if (v1ok) *(float2*)(arow1 + gj) = make_float2(acc[f][2], acc[f][3]);
    }

    // ---- ctx = attn @ V: repack acc frags as A frags, B via ldmatrix.trans ----
    float cacc[8][4];
#pragma unroll
    for (int nf = 0; nf < 8; nf++)
#pragma unroll
        for (int r = 0; r < 4; r++) cacc[nf][r] = 0.f;

#pragma unroll
    for (int kf = 0; kf < 13; kf++) {
        uint32_t ahi[4], alo[4];
        split2(acc[2 * kf][0], acc[2 * kf][1], ahi[0], alo[0]);
        split2(acc[2 * kf][2], acc[2 * kf][3], ahi[1], alo[1]);
        if (kf < 12) {
            split2(acc[2 * kf + 1][0], acc[2 * kf + 1][1], ahi[2], alo[2]);
            split2(acc[2 * kf + 1][2], acc[2 * kf + 1][3], ahi[3], alo[3]);
        } else {
            ahi[2] = alo[2] = ahi[3] = alo[3] = 0u;
        }
#pragma unroll
        for (int nb = 0; nb < 4; nb++) {
            int row = kf * 16 + (lane & 15);
            int ch  = nb * 2 + (lane >> 4);
            uint32_t so = swz128(row, ch);
            uint32_t h0, h1, h2, h3, l0, l1, l2, l3;
            ldsm_x4_t(h0, h1, h2, h3, sb + FA_VHI + so);
            ldsm_x4_t(l0, l1, l2, l3, sb + FA_VLO + so);
            uint32_t bh0[2] = {h0, h1}, bl0[2] = {l0, l1};
            uint32_t bh1[2] = {h2, h3}, bl1[2] = {l2, l3};
            mma_bf16(cacc[nb * 2], ahi, bh0);
            mma_bf16(cacc[nb * 2], ahi, bl0);
            mma_bf16(cacc[nb * 2], alo, bh0);
            mma_bf16(cacc[nb * 2 + 1], ahi, bh1);
            mma_bf16(cacc[nb * 2 + 1], ahi, bl1);
            mma_bf16(cacc[nb * 2 + 1], alo, bh1);
        }
    }

    const int h = bh & 15;
    float* crow0 = g_ctx + ((size_t)b * S_ + gi0) * DM_ + h * DK_;
    float* crow1 = g_ctx + ((size_t)b * S_ + gi1) * DM_ + h * DK_;
#pragma unroll
    for (int nf = 0; nf < 8; nf++) {
        int n = nf * 8 + c2;
        if (v0ok) *(float2*)(crow0 + n) = make_float2(cacc[nf][0], cacc[nf][1]);
        if (v1ok) *(float2*)(crow1 + n) = make_float2(cacc[nf][2], cacc[nf][3]);
    }
}

// ---------------------------------------------------------------------------
extern "C" void kernel_launch(void* const* d_in, const int* in_sizes, int n_in,
                              void* d_out, int out_size)
{
    const float* x    = (const float*)d_in[0];
    const int*   mask = (const int*)  d_in[1];
    const float* wq   = (const float*)d_in[2];
    const float* bq   = (const float*)d_in[3];
    const float* wk   = (const float*)d_in[4];
    const float* bk   = (const float*)d_in[5];
    const float* wv   = (const float*)d_in[6];
    const float* bv   = (const float*)d_in[7];
    const float* wo   = (const float*)d_in[8];
    const float* bo   = (const float*)d_in[9];

    void *pQ, *pK, *pV, *pCtx, *pAttnFb, *pOutFb;
    cudaGetSymbolAddress(&pQ, g_Q);
    cudaGetSymbolAddress(&pK, g_K);
    cudaGetSymbolAddress(&pV, g_V);
    cudaGetSymbolAddress(&pCtx, g_ctx);
    cudaGetSymbolAddress(&pAttnFb, g_attn_fb);
    cudaGetSymbolAddress(&pOutFb, g_out_fb);

    float* outp;
    float* attnp;
    size_t osz = (size_t)out_size;
    if (osz >= OUT_N + ATTN_N) {
        outp  = (float*)d_out;
        attnp = (float*)d_out + OUT_N;
    } else if (osz == ATTN_N) {
        attnp = (float*)d_out;
        outp  = (float*)pOutFb;
    } else {
        outp  = (float*)d_out;
        attnp = (float*)pAttnFb;
    }

    cudaFuncSetAttribute(gemm_mma<0>, cudaFuncAttributeMaxDynamicSharedMemorySize, GEMM_SMEM);
    cudaFuncSetAttribute(gemm_mma<1>, cudaFuncAttributeMaxDynamicSharedMemorySize, GEMM_SMEM);
    cudaFuncSetAttribute(attn_fused, cudaFuncAttributeMaxDynamicSharedMemorySize, FA_SMEM);

    dim3 gProj(DM_ / 128, MROWS / 128);   // (8, 100)
    gemm_mma<0><<<gProj, 256, GEMM_SMEM>>>(x, wq, bq, (float*)pQ);
    gemm_mma<0><<<gProj, 256, GEMM_SMEM>>>(x, wk, bk, (float*)pK);
    gemm_mma<0><<<gProj, 256, GEMM_SMEM>>>(x, wv, bv, (float*)pV);

    dim3 gFA(4, BH_);                     // q-tiles x (b*h)
    attn_fused<<<gFA, 128, FA_SMEM>>>(mask, attnp);

    gemm_mma<1><<<gProj, 256, GEMM_SMEM>>>((const float*)pCtx, wo, bo, outp);
}

// round 5
// speedup vs baseline: 2.6459x; 1.3397x over previous
#include <cuda_runtime.h>
#include <cuda_bf16.h>
#include <math.h>
#include <stdint.h>

// Problem constants
#define B_    64
#define S_    200
#define H_    16
#define DK_   64
#define DM_   1024
#define MROWS (B_ * S_)          // 12800
#define BH_   (B_ * H_)          // 1024
#define OUT_N  ((size_t)MROWS * DM_)       // 13107200
#define ATTN_N ((size_t)BH_ * S_ * S_)     // 40960000

// Scratch (allocation-free rule: __device__ globals)
__device__ __nv_bfloat16 g_xhi[MROWS * DM_];
__device__ __nv_bfloat16 g_xlo[MROWS * DM_];
__device__ __nv_bfloat16 g_whi[4][DM_ * DM_];
__device__ __nv_bfloat16 g_wlo[4][DM_ * DM_];
__device__ __nv_bfloat16 g_Qhi[BH_ * S_ * DK_];
__device__ __nv_bfloat16 g_Qlo[BH_ * S_ * DK_];
__device__ __nv_bfloat16 g_Khi[BH_ * S_ * DK_];
__device__ __nv_bfloat16 g_Klo[BH_ * S_ * DK_];
__device__ __nv_bfloat16 g_Vhi[BH_ * S_ * DK_];
__device__ __nv_bfloat16 g_Vlo[BH_ * S_ * DK_];
__device__ __nv_bfloat16 g_ctxhi[MROWS * DM_];
__device__ __nv_bfloat16 g_ctxlo[MROWS * DM_];
__device__ float g_attn_fb[BH_ * S_ * S_];
__device__ float g_out_fb[MROWS * DM_];

// ===========================================================================
// Helpers
// ===========================================================================
__device__ __forceinline__ uint32_t smem_to_u32(const void* p) {
    uint32_t a;
    asm("{ .reg .u64 t; cvta.to.shared.u64 t, %1; cvt.u32.u64 %0, t; }"
        : "=r"(a) : "l"(p));
    return a;
}

__device__ __forceinline__ void ldsm_x4(uint32_t& r0, uint32_t& r1,
                                        uint32_t& r2, uint32_t& r3, uint32_t addr) {
    asm volatile("ldmatrix.sync.aligned.m8n8.x4.shared.b16 {%0,%1,%2,%3}, [%4];"
                 : "=r"(r0), "=r"(r1), "=r"(r2), "=r"(r3) : "r"(addr));
}
__device__ __forceinline__ void ldsm_x4_t(uint32_t& r0, uint32_t& r1,
                                          uint32_t& r2, uint32_t& r3, uint32_t addr) {
    asm volatile("ldmatrix.sync.aligned.m8n8.x4.trans.shared.b16 {%0,%1,%2,%3}, [%4];"
                 : "=r"(r0), "=r"(r1), "=r"(r2), "=r"(r3) : "r"(addr));
}

__device__ __forceinline__ void mma_bf16(float* d, const uint32_t* a, const uint32_t* b) {
    asm volatile(
        "mma.sync.aligned.m16n8k16.row.col.f32.bf16.bf16.f32 "
        "{%0,%1,%2,%3}, {%4,%5,%6,%7}, {%8,%9}, {%0,%1,%2,%3};"
        : "+f"(d[0]), "+f"(d[1]), "+f"(d[2]), "+f"(d[3])
        : "r"(a[0]), "r"(a[1]), "r"(a[2]), "r"(a[3]), "r"(b[0]), "r"(b[1]));
}

#define STS128(addr, r0, r1, r2, r3) \
    asm volatile("st.shared.v4.b32 [%0], {%1,%2,%3,%4};" \
        :: "r"(addr), "r"(r0), "r"(r1), "r"(r2), "r"(r3) : "memory")

#define CP_ASYNC16(sm, gp) \
    asm volatile("{ .reg .u64 g; cvta.to.global.u64 g, %1; " \
                 "cp.async.cg.shared.global [%0], [g], 16; }" \
                 :: "r"(sm), "l"(gp) : "memory")
#define CP_COMMIT() asm volatile("cp.async.commit_group;" ::: "memory")
#define CP_WAIT0()  asm volatile("cp.async.wait_group 0;" ::: "memory")

// hi/lo bf16 split of a float pair, packed as 2x uint32 (bf16x2)
__device__ __forceinline__ void split2(float x, float y, uint32_t& hi, uint32_t& lo) {
    __nv_bfloat162 h = __floats2bfloat162_rn(x, y);
    float rx = x - __bfloat162float(h.x);
    float ry = y - __bfloat162float(h.y);
    __nv_bfloat162 l = __floats2bfloat162_rn(rx, ry);
    hi = *(uint32_t*)&h;
    lo = *(uint32_t*)&l;
}

// 64B-row swizzle (gemm): 4 chunks of 16B; chunk ^= (row>>1)&3
__device__ __forceinline__ uint32_t swz(int row, int chunk) {
    return (uint32_t)(row * 64 + ((chunk ^ ((row >> 1) & 3)) << 4));
}
// 128B-row swizzle (attention): 8 chunks of 16B; chunk ^= row&7
__device__ __forceinline__ uint32_t swz128(int row, int chunk) {
    return (uint32_t)(row * 128 + ((chunk ^ (row & 7)) << 4));
}

// ===========================================================================
// Split kernel: float -> bf16 hi/lo (vector of 8 per thread)
// ===========================================================================
__global__ void __launch_bounds__(256) split_kernel(
    const float* __restrict__ src, __nv_bfloat16* __restrict__ hi,
    __nv_bfloat16* __restrict__ lo, int n)
{
    int i = (blockIdx.x * 256 + threadIdx.x) * 8;
    if (i >= n) return;
    float4 v0 = *(const float4*)(src + i);
    float4 v1 = *(const float4*)(src + i + 4);
    uint32_t h[4], l[4];
    split2(v0.x, v0.y, h[0], l[0]); split2(v0.z, v0.w, h[1], l[1]);
    split2(v1.x, v1.y, h[2], l[2]); split2(v1.z, v1.w, h[3], l[3]);
    *(uint4*)(hi + i) = make_uint4(h[0], h[1], h[2], h[3]);
    *(uint4*)(lo + i) = make_uint4(l[0], l[1], l[2], l[3]);
}

// ===========================================================================
// bf16 hi/lo GEMM via mma.sync on pre-split inputs.
// C = A[M,1024] @ W^T[1024,1024] + bias. CTA 128x128, 8 warps, K-chunk 32,
// cp.async double buffer. OUT_MODE 0: bf16 hi/lo scatter to [b,h,s,dk].
// OUT_MODE 1: fp32 row-major.
// ===========================================================================
#define ST_AHI(s)  ((uint32_t)(s) * 32768u + 0u)
#define ST_ALO(s)  ((uint32_t)(s) * 32768u + 8192u)
#define ST_BHI(s)  ((uint32_t)(s) * 32768u + 16384u)
#define ST_BLO(s)  ((uint32_t)(s) * 32768u + 24576u)
#define GEMM_SMEM  65536

template <int OUT_MODE>
__global__ void __launch_bounds__(256, 1) gemm_mma(
    const __nv_bfloat16* __restrict__ Ahi, const __nv_bfloat16* __restrict__ Alo,
    const __nv_bfloat16* __restrict__ Whi, const __nv_bfloat16* __restrict__ Wlo,
    const float* __restrict__ bias,
    __nv_bfloat16* __restrict__ Chi, __nv_bfloat16* __restrict__ Clo,
    float* __restrict__ Cf)
{
    extern __shared__ char smem[];
    const uint32_t sb = smem_to_u32(smem);
    const int tid  = threadIdx.x;
    const int lane = tid & 31;
    const int wid  = tid >> 5;
    const int wm   = wid >> 2;
    const int wn   = wid & 3;
    const int m0   = blockIdx.y * 128;
    const int n0   = blockIdx.x * 128;

    float acc[4][4][4];
#pragma unroll
    for (int i = 0; i < 4; i++)
#pragma unroll
        for (int j = 0; j < 4; j++)
#pragma unroll
            for (int r = 0; r < 4; r++) acc[i][j][r] = 0.f;

    // chunk ids for this thread: c0 in [0,256), c1 in [256,512)
    const int c0 = tid, c1 = tid + 256;
    const int r0c = c0 >> 2, cc0 = c0 & 3;
    const int r1c = c1 >> 2, cc1 = c1 & 3;
    const uint32_t sw0 = swz(r0c, cc0), sw1 = swz(r1c, cc1);

#define ISSUE_STAGE(st, kt_) do { \
    size_t ka = (size_t)(kt_) * 32; \
    const __nv_bfloat16* a0 = Ahi + (size_t)(m0 + r0c) * DM_ + ka + cc0 * 8; \
    const __nv_bfloat16* a1 = Ahi + (size_t)(m0 + r1c) * DM_ + ka + cc1 * 8; \
    CP_ASYNC16(sb + ST_AHI(st) + sw0, a0); \
    CP_ASYNC16(sb + ST_AHI(st) + sw1, a1); \
    a0 = Alo + (size_t)(m0 + r0c) * DM_ + ka + cc0 * 8; \
    a1 = Alo + (size_t)(m0 + r1c) * DM_ + ka + cc1 * 8; \
    CP_ASYNC16(sb + ST_ALO(st) + sw0, a0); \
    CP_ASYNC16(sb + ST_ALO(st) + sw1, a1); \
    a0 = Whi + (size_t)(n0 + r0c) * DM_ + ka + cc0 * 8; \
    a1 = Whi + (size_t)(n0 + r1c) * DM_ + ka + cc1 * 8; \
    CP_ASYNC16(sb + ST_BHI(st) + sw0, a0); \
    CP_ASYNC16(sb + ST_BHI(st) + sw1, a1); \
    a0 = Wlo + (size_t)(n0 + r0c) * DM_ + ka + cc0 * 8; \
    a1 = Wlo + (size_t)(n0 + r1c) * DM_ + ka + cc1 * 8; \
    CP_ASYNC16(sb + ST_BLO(st) + sw0, a0); \
    CP_ASYNC16(sb + ST_BLO(st) + sw1, a1); \
} while (0)

    ISSUE_STAGE(0, 0);
    CP_COMMIT();
    CP_WAIT0();
    __syncthreads();

    const int a_row_in = lane & 15;
    const int a_kh     = lane >> 4;
    const int b_col_in = (lane & 7) + ((lane >> 4) << 3);
    const int b_kh     = (lane >> 3) & 1;

    for (int kt = 0; kt < 32; kt++) {
        const int cur = kt & 1;

        if (kt < 31) {
            ISSUE_STAGE((kt + 1) & 1, kt + 1);
            CP_COMMIT();
        }

        const uint32_t ahiB = sb + ST_AHI(cur), aloB = sb + ST_ALO(cur);
        const uint32_t bhiB = sb + ST_BHI(cur), bloB = sb + ST_BLO(cur);

#pragma unroll
        for (int ks = 0; ks < 2; ks++) {
            uint32_t ahi[4][4], alo[4][4];
#pragma unroll
            for (int mf = 0; mf < 4; mf++) {
                int row = wm * 64 + mf * 16 + a_row_in;
                int ch  = ks * 2 + a_kh;
                uint32_t so = swz(row, ch);
                ldsm_x4(ahi[mf][0], ahi[mf][1], ahi[mf][2], ahi[mf][3], ahiB + so);
                ldsm_x4(alo[mf][0], alo[mf][1], alo[mf][2], alo[mf][3], aloB + so);
            }
            uint32_t bhi[4][2], blo[4][2];
#pragma unroll
            for (int bi = 0; bi < 2; bi++) {
                int col = wn * 32 + bi * 16 + b_col_in;
                int ch  = ks * 2 + b_kh;
                uint32_t so = swz(col, ch);
                uint32_t r0, r1, r2, r3;
                ldsm_x4(r0, r1, r2, r3, bhiB + so);
                bhi[bi * 2][0] = r0; bhi[bi * 2][1] = r1;
                bhi[bi * 2 + 1][0] = r2; bhi[bi * 2 + 1][1] = r3;
                ldsm_x4(r0, r1, r2, r3, bloB + so);
                blo[bi * 2][0] = r0; blo[bi * 2][1] = r1;
                blo[bi * 2 + 1][0] = r2; blo[bi * 2 + 1][1] = r3;
            }
#pragma unroll
            for (int mf = 0; mf < 4; mf++)
#pragma unroll
                for (int nf = 0; nf < 4; nf++) {
                    mma_bf16(acc[mf][nf], ahi[mf], bhi[nf]);
                    mma_bf16(acc[mf][nf], ahi[mf], blo[nf]);
                    mma_bf16(acc[mf][nf], alo[mf], bhi[nf]);
                }
        }
        if (kt < 31) {
            CP_WAIT0();
            __syncthreads();
        }
    }
#undef ISSUE_STAGE

    const int g  = lane >> 2;
    const int c2 = (lane & 3) * 2;
#pragma unroll
    for (int nf = 0; nf < 4; nf++) {
        const int n = n0 + wn * 32 + nf * 8 + c2;
        const float b0 = bias[n], b1 = bias[n + 1];
#pragma unroll
        for (int mf = 0; mf < 4; mf++) {
            const int m = m0 + wm * 64 + mf * 16 + g;
            if (OUT_MODE == 0) {
                int hh = n >> 6;
                int dk = n & 63;
                uint32_t hi0, lo0, hi1, lo1;
                split2(acc[mf][nf][0] + b0, acc[mf][nf][1] + b1, hi0, lo0);
                split2(acc[mf][nf][2] + b0, acc[mf][nf][3] + b1, hi1, lo1);
                int bb = m / S_;
                int ss = m - bb * S_;
                size_t off0 = (((size_t)bb * H_ + hh) * S_ + ss) * DK_ + dk;
                *(uint32_t*)(Chi + off0) = hi0;
                *(uint32_t*)(Clo + off0) = lo0;
                int m2 = m + 8;
                int bb2 = m2 / S_;
                int ss2 = m2 - bb2 * S_;
                size_t off1 = (((size_t)bb2 * H_ + hh) * S_ + ss2) * DK_ + dk;
                *(uint32_t*)(Chi + off1) = hi1;
                *(uint32_t*)(Clo + off1) = lo1;
            } else {
                float2 v0 = make_float2(acc[mf][nf][0] + b0, acc[mf][nf][1] + b1);
                float2 v1 = make_float2(acc[mf][nf][2] + b0, acc[mf][nf][3] + b1);
                *(float2*)(Cf + (size_t)m * DM_ + n)       = v0;
                *(float2*)(Cf + (size_t)(m + 8) * DM_ + n) = v1;
            }
        }
    }
}

// ===========================================================================
// Fused attention: CTA = (64 q-rows, bh). 128 threads. Q frags from gmem,
// K/V (pre-split bf16) via cp.async. softmax in regs; attn->gmem fp32;
// ctx = attn@V -> bf16 hi/lo scatter.
// ===========================================================================
#define FK_HI   0u
#define FK_LO   26624u
#define FV_HI   53248u
#define FV_LO   79872u
#define FA_SMEM 106496

__global__ void __launch_bounds__(128, 2) attn_fused(
    const int* __restrict__ mask, float* __restrict__ attn)
{
    extern __shared__ char smem[];
    const uint32_t sb = smem_to_u32(smem);
    const int tid  = threadIdx.x;
    const int lane = tid & 31;
    const int w    = tid >> 5;
    const int qt   = blockIdx.x;          // 0..3
    const int bh   = blockIdx.y;
    const int b    = bh >> 4;

    const __nv_bfloat16* Khi = g_Khi + (size_t)bh * S_ * DK_;
    const __nv_bfloat16* Klo = g_Klo + (size_t)bh * S_ * DK_;
    const __nv_bfloat16* Vhi = g_Vhi + (size_t)bh * S_ * DK_;
    const __nv_bfloat16* Vlo = g_Vlo + (size_t)bh * S_ * DK_;
    const __nv_bfloat16* Qhi = g_Qhi + (size_t)bh * S_ * DK_;
    const __nv_bfloat16* Qlo = g_Qlo + (size_t)bh * S_ * DK_;

    // ---- cp.async K/V hi/lo (200 rows x 8 chunks of 16B each) ----
    for (int c = tid; c < 1600; c += 128) {
        int r = c >> 3, cc = c & 7;
        uint32_t so = swz128(r, cc);
        size_t go = (size_t)r * DK_ + cc * 8;
        CP_ASYNC16(sb + FK_HI + so, Khi + go);
        CP_ASYNC16(sb + FK_LO + so, Klo + go);
        CP_ASYNC16(sb + FV_HI + so, Vhi + go);
        CP_ASYNC16(sb + FV_LO + so, Vlo + go);
    }
    CP_COMMIT();
    // zero-pad rows 200..207
    if (tid < 64) {
        int r = 200 + (tid >> 3), cc = tid & 7;
        uint32_t so = swz128(r, cc);
        STS128(sb + FK_HI + so, 0u, 0u, 0u, 0u);
        STS128(sb + FK_LO + so, 0u, 0u, 0u, 0u);
        STS128(sb + FV_HI + so, 0u, 0u, 0u, 0u);
        STS128(sb + FV_LO + so, 0u, 0u, 0u, 0u);
    }
    CP_WAIT0();
    __syncthreads();

    // ---- Scores ----
    float acc[25][4];
#pragma unroll
    for (int f = 0; f < 25; f++)
#pragma unroll
        for (int r = 0; r < 4; r++) acc[f][r] = 0.f;

    const int g  = lane >> 2;
    const int c2 = (lane & 3) * 2;
    const int b_col_in = (lane & 7) + ((lane >> 4) << 3);
    const int b_kh     = (lane >> 3) & 1;

    const int qr0 = qt * 64 + w * 16 + g;
    const int qr1 = qr0 + 8;
    const size_t qo0 = (size_t)min(qr0, S_ - 1) * DK_;
    const size_t qo1 = (size_t)min(qr1, S_ - 1) * DK_;

    for (int kb = 0; kb < 4; kb++) {
        const int col = kb * 16 + c2;
        uint32_t ahi[4], alo[4];
        ahi[0] = *(const uint32_t*)(Qhi + qo0 + col);
        ahi[1] = *(const uint32_t*)(Qhi + qo1 + col);
        ahi[2] = *(const uint32_t*)(Qhi + qo0 + col + 8);
        ahi[3] = *(const uint32_t*)(Qhi + qo1 + col + 8);
        alo[0] = *(const uint32_t*)(Qlo + qo0 + col);
        alo[1] = *(const uint32_t*)(Qlo + qo1 + col);
        alo[2] = *(const uint32_t*)(Qlo + qo0 + col + 8);
        alo[3] = *(const uint32_t*)(Qlo + qo1 + col + 8);
#pragma unroll
        for (int nb = 0; nb < 13; nb++) {
            int row = nb * 16 + b_col_in;
            int ch  = kb * 2 + b_kh;
            uint32_t so = swz128(row, ch);
            uint32_t h0, h1, h2, h3, l0, l1, l2, l3;
            ldsm_x4(h0, h1, h2, h3, sb + FK_HI + so);
            ldsm_x4(l0, l1, l2, l3, sb + FK_LO + so);
            uint32_t bh0[2] = {h0, h1}, bl0[2] = {l0, l1};
            mma_bf16(acc[nb * 2], ahi, bh0);
            mma_bf16(acc[nb * 2], ahi, bl0);
            mma_bf16(acc[nb * 2], alo, bh0);
            if (nb < 12) {
                uint32_t bh1[2] = {h2, h3}, bl1[2] = {l2, l3};
                mma_bf16(acc[nb * 2 + 1], ahi, bh1);
                mma_bf16(acc[nb * 2 + 1], ahi, bl1);
                mma_bf16(acc[nb * 2 + 1], alo, bh1);
            }
        }
    }

    // ---- scale + temporal bias + mask + softmax in registers ----
    const int gi0 = qr0;
    const int gi1 = qr1;
    const bool v0ok = (gi0 < S_);
    const bool v1ok = (gi1 < S_);
    const int* mrow0 = mask + (size_t)b * S_ * S_ + (size_t)gi0 * S_;
    const int* mrow1 = mask + (size_t)b * S_ * S_ + (size_t)gi1 * S_;
    const float BC = -0.1f / 200.0f;

    float mx0 = -1e30f, mx1 = -1e30f;
#pragma unroll
    for (int f = 0; f < 25; f++) {
        int gj = f * 8 + c2;
        int2 m0v = v0ok ? *(const int2*)(mrow0 + gj) : make_int2(1, 1);
        int2 m1v = v1ok ? *(const int2*)(mrow1 + gj) : make_int2(1, 1);
        float t00 = BC * fabsf((float)(gi0 - gj));
        float t01 = BC * fabsf((float)(gi0 - gj - 1));
        float t10 = BC * fabsf((float)(gi1 - gj));
        float t11 = BC * fabsf((float)(gi1 - gj - 1));
        acc[f][0] = (m0v.x == 0) ? -1e9f : fmaf(acc[f][0], 0.125f, t00);
        acc[f][1] = (m0v.y == 0) ? -1e9f : fmaf(acc[f][1], 0.125f, t01);
        acc[f][2] = (m1v.x == 0) ? -1e9f : fmaf(acc[f][2], 0.125f, t10);
        acc[f][3] = (m1v.y == 0) ? -1e9f : fmaf(acc[f][3], 0.125f, t11);
        mx0 = fmaxf(mx0, fmaxf(acc[f][0], acc[f][1]));
        mx1 = fmaxf(mx1, fmaxf(acc[f][2], acc[f][3]));
    }
    mx0 = fmaxf(mx0, __shfl_xor_sync(0xffffffffu, mx0, 1));
    mx0 = fmaxf(mx0, __shfl_xor_sync(0xffffffffu, mx0, 2));
    mx1 = fmaxf(mx1, __shfl_xor_sync(0xffffffffu, mx1, 1));
    mx1 = fmaxf(mx1, __shfl_xor_sync(0xffffffffu, mx1, 2));

    float s0 = 0.f, s1 = 0.f;
#pragma unroll
    for (int f = 0; f < 25; f++) {
        acc[f][0] = expf(acc[f][0] - mx0);
        acc[f][1] = expf(acc[f][1] - mx0);
        acc[f][2] = expf(acc[f][2] - mx1);
        acc[f][3] = expf(acc[f][3] - mx1);
        s0 += acc[f][0] + acc[f][1];
        s1 += acc[f][2] + acc[f][3];
    }
    s0 += __shfl_xor_sync(0xffffffffu, s0, 1);
    s0 += __shfl_xor_sync(0xffffffffu, s0, 2);
    s1 += __shfl_xor_sync(0xffffffffu, s1, 1);
    s1 += __shfl_xor_sync(0xffffffffu, s1, 2);
    const float i0 = 1.f / s0;
    const float i1 = 1.f / s1;

    float* arow0 = attn + (size_t)bh * S_ * S_ + (size_t)gi0 * S_;
    float* arow1 = attn + (size_t)bh * S_ * S_ + (size_t)gi1 * S_;
#pragma unroll
    for (int f = 0; f < 25; f++) {
        int gj = f * 8 + c2;
        acc[f][0] *= i0; acc[f][1] *= i0;
        acc[f][2] *= i1; acc[f][3] *= i1;
        if (v0ok) *(float2*)(arow0 + gj) = make_float2(acc[f][0], acc[f][1]);
        if (v1ok) *(float2*)(arow1 + gj) = make_float2(acc[f][2], acc[f][3]);
    }

    // ---- ctx = attn @ V ----
    float cacc[8][4];
#pragma unroll
    for (int nf = 0; nf < 8; nf++)
#pragma unroll
        for (int r = 0; r < 4; r++) cacc[nf][r] = 0.f;

#pragma unroll
    for (int kf = 0; kf < 13; kf++) {
        uint32_t ahi[4], alo[4];
        split2(acc[2 * kf][0], acc[2 * kf][1], ahi[0], alo[0]);
        split2(acc[2 * kf][2], acc[2 * kf][3], ahi[1], alo[1]);
        if (kf < 12) {
            split2(acc[2 * kf + 1][0], acc[2 * kf + 1][1], ahi[2], alo[2]);
            split2(acc[2 * kf + 1][2], acc[2 * kf + 1][3], ahi[3], alo[3]);
        } else {
            ahi[2] = alo[2] = ahi[3] = alo[3] = 0u;
        }
#pragma unroll
        for (int nb = 0; nb < 4; nb++) {
            int row = kf * 16 + (lane & 15);
            int ch  = nb * 2 + (lane >> 4);
            uint32_t so = swz128(row, ch);
            uint32_t h0, h1, h2, h3, l0, l1, l2, l3;
            ldsm_x4_t(h0, h1, h2, h3, sb + FV_HI + so);
            ldsm_x4_t(l0, l1, l2, l3, sb + FV_LO + so);
            uint32_t bh0[2] = {h0, h1}, bl0[2] = {l0, l1};
            uint32_t bh1[2] = {h2, h3}, bl1[2] = {l2, l3};
            mma_bf16(cacc[nb * 2], ahi, bh0);
            mma_bf16(cacc[nb * 2], ahi, bl0);
            mma_bf16(cacc[nb * 2], alo, bh0);
            mma_bf16(cacc[nb * 2 + 1], ahi, bh1);
            mma_bf16(cacc[nb * 2 + 1], ahi, bl1);
            mma_bf16(cacc[nb * 2 + 1], alo, bh1);
        }
    }

    const int h = bh & 15;
    __nv_bfloat16* chi0 = g_ctxhi + ((size_t)b * S_ + gi0) * DM_ + h * DK_;
    __nv_bfloat16* clo0 = g_ctxlo + ((size_t)b * S_ + gi0) * DM_ + h * DK_;
    __nv_bfloat16* chi1 = g_ctxhi + ((size_t)b * S_ + gi1) * DM_ + h * DK_;
    __nv_bfloat16* clo1 = g_ctxlo + ((size_t)b * S_ + gi1) * DM_ + h * DK_;
#pragma unroll
    for (int nf = 0; nf < 8; nf++) {
        int n = nf * 8 + c2;
        uint32_t hi0, lo0, hi1, lo1;
        split2(cacc[nf][0], cacc[nf][1], hi0, lo0);
        split2(cacc[nf][2], cacc[nf][3], hi1, lo1);
        if (v0ok) { *(uint32_t*)(chi0 + n) = hi0; *(uint32_t*)(clo0 + n) = lo0; }
        if (v1ok) { *(uint32_t*)(chi1 + n) = hi1; *(uint32_t*)(clo1 + n) = lo1; }
    }
}

// ---------------------------------------------------------------------------
extern "C" void kernel_launch(void* const* d_in, const int* in_sizes, int n_in,
                              void* d_out, int out_size)
{
    const float* x    = (const float*)d_in[0];
    const int*   mask = (const int*)  d_in[1];
    const float* wq   = (const float*)d_in[2];
    const float* bq   = (const float*)d_in[3];
    const float* wk   = (const float*)d_in[4];
    const float* bk   = (const float*)d_in[5];
    const float* wv   = (const float*)d_in[6];
    const float* bv   = (const float*)d_in[7];
    const float* wo   = (const float*)d_in[8];
    const float* bo   = (const float*)d_in[9];

    void *pxh, *pxl, *pwh, *pwl;
    void *pQh, *pQl, *pKh, *pKl, *pVh, *pVl, *pch, *pcl, *pAttnFb, *pOutFb;
    cudaGetSymbolAddress(&pxh, g_xhi);  cudaGetSymbolAddress(&pxl, g_xlo);
    cudaGetSymbolAddress(&pwh, g_whi);  cudaGetSymbolAddress(&pwl, g_wlo);
    cudaGetSymbolAddress(&pQh, g_Qhi);  cudaGetSymbolAddress(&pQl, g_Qlo);
    cudaGetSymbolAddress(&pKh, g_Khi);  cudaGetSymbolAddress(&pKl, g_Klo);
    cudaGetSymbolAddress(&pVh, g_Vhi);  cudaGetSymbolAddress(&pVl, g_Vlo);
    cudaGetSymbolAddress(&pch, g_ctxhi); cudaGetSymbolAddress(&pcl, g_ctxlo);
    cudaGetSymbolAddress(&pAttnFb, g_attn_fb);
    cudaGetSymbolAddress(&pOutFb, g_out_fb);

    __nv_bfloat16* xh = (__nv_bfloat16*)pxh;
    __nv_bfloat16* xl = (__nv_bfloat16*)pxl;
    __nv_bfloat16* wh = (__nv_bfloat16*)pwh;
    __nv_bfloat16* wl = (__nv_bfloat16*)pwl;

    float* outp;
    float* attnp;
    size_t osz = (size_t)out_size;
    if (osz >= OUT_N + ATTN_N) {
        outp  = (float*)d_out;
        attnp = (float*)d_out + OUT_N;
    } else if (osz == ATTN_N) {
        attnp = (float*)d_out;
        outp  = (float*)pOutFb;
    } else {
        outp  = (float*)d_out;
        attnp = (float*)pAttnFb;
    }

    cudaFuncSetAttribute(gemm_mma<0>, cudaFuncAttributeMaxDynamicSharedMemorySize, GEMM_SMEM);
    cudaFuncSetAttribute(gemm_mma<1>, cudaFuncAttributeMaxDynamicSharedMemorySize, GEMM_SMEM);
    cudaFuncSetAttribute(attn_fused, cudaFuncAttributeMaxDynamicSharedMemorySize, FA_SMEM);

    // Split inputs to bf16 hi/lo
    const int WN = DM_ * DM_;
    split_kernel<<<MROWS * DM_ / 2048, 256>>>(x,  xh, xl, MROWS * DM_);
    split_kernel<<<WN / 2048, 256>>>(wq, wh + 0 * (size_t)WN, wl + 0 * (size_t)WN, WN);
    split_kernel<<<WN / 2048, 256>>>(wk, wh + 1 * (size_t)WN, wl + 1 * (size_t)WN, WN);
    split_kernel<<<WN / 2048, 256>>>(wv, wh + 2 * (size_t)WN, wl + 2 * (size_t)WN, WN);
    split_kernel<<<WN / 2048, 256>>>(wo, wh + 3 * (size_t)WN, wl + 3 * (size_t)WN, WN);

    dim3 gProj(DM_ / 128, MROWS / 128);   // (8, 100)
    gemm_mma<0><<<gProj, 256, GEMM_SMEM>>>(xh, xl, wh + 0 * (size_t)WN, wl + 0 * (size_t)WN,
        bq, (__nv_bfloat16*)pQh, (__nv_bfloat16*)pQl, nullptr);
    gemm_mma<0><<<gProj, 256, GEMM_SMEM>>>(xh, xl, wh + 1 * (size_t)WN, wl + 1 * (size_t)WN,
        bk, (__nv_bfloat16*)pKh, (__nv_bfloat16*)pKl, nullptr);
    gemm_mma<0><<<gProj, 256, GEMM_SMEM>>>(xh, xl, wh + 2 * (size_t)WN, wl + 2 * (size_t)WN,
        bv, (__nv_bfloat16*)pVh, (__nv_bfloat16*)pVl, nullptr);

    dim3 gFA(4, BH_);
    attn_fused<<<gFA, 128, FA_SMEM>>>(mask, attnp);

    gemm_mma<1><<<gProj, 256, GEMM_SMEM>>>((__nv_bfloat16*)pch, (__nv_bfloat16*)pcl,
        wh + 3 * (size_t)WN, wl + 3 * (size_t)WN, bo, nullptr, nullptr, outp);
}